// round 9
// baseline (speedup 1.0000x reference)
#include <cuda_runtime.h>
#include <cstdint>

#define T_STEPS 512
#define B_N 64
#define I_N 128
#define H_N 512
#define O_N 128
#define KLAG 32
#define NCTA 128
#define NTHR 1024

// d_out layout: outputs [512,64,128] | h_last [64,512] | hc_last [32,64,512]
#define OUT_HLAST 4194304
#define OUT_HC    4227072

// smem byte offsets
#define OFF_XBUF 0u
#define OFF_HB   32768u          // 3 x 32KB ring
#define OFF_RED  32768u          // aliases HB (512 slots x 13 float2 = 53KB)
#define OFF_WIO  131072u         // [640][4] float4 (wi,wi,wo,wo)
#define OFF_WC2  172032u         // [640][4] float2 (wc,wc)
#define OFF_CH   192512u         // chist [32][4][32] float2
#define OFF_WD   225280u         // wd [32][4] float
#define SMEM_TOTAL 225792

// ---------------- device scratch ----------------
__device__ float g_xT[(size_t)T_STEPS * I_N * B_N];      // [t][i][b]
__device__ float g_HallT[(size_t)T_STEPS * H_N * B_N];   // [t][h][b]
__device__ float g_zero[H_N * B_N];                      // never written
__device__ unsigned g_flags[NCTA * 32];                  // 128B-strided flags (monotonic)

// ---------------- helpers ----------------
union F2U { float2 f; unsigned long long u; };

__device__ __forceinline__ float2 ffma2(float2 a, float2 b, float2 c) {
    F2U ua, ub, uc, ud;
    ua.f = a; ub.f = b; uc.f = c;
    asm("fma.rn.f32x2 %0, %1, %2, %3;" : "=l"(ud.u) : "l"(ua.u), "l"(ub.u), "l"(uc.u));
    return ud.f;
}
__device__ __forceinline__ uint32_t smem_u32(const void* p) {
    return (uint32_t)__cvta_generic_to_shared(p);
}
__device__ __forceinline__ void cp16(uint32_t dst, const void* src) {
    asm volatile("cp.async.cg.shared.global [%0], [%1], 16;" :: "r"(dst), "l"(src));
}
#define CP_COMMIT() asm volatile("cp.async.commit_group;")
#define CP_WAIT(n)  asm volatile("cp.async.wait_group %0;" :: "n"(n))

__device__ __forceinline__ float sigf(float x) { return 1.0f / (1.0f + __expf(-x)); }
__device__ __forceinline__ float tanh_f(float x) {
    float e = __expf(2.0f * x);
    return 1.0f - __fdividef(2.0f, e + 1.0f);
}
__device__ __forceinline__ void flag_store(unsigned* p, unsigned v) {
    asm volatile("st.release.gpu.global.u32 [%0], %1;" :: "l"(p), "r"(v) : "memory");
}
__device__ __forceinline__ unsigned flag_load(const unsigned* p) {
    unsigned v;
    asm volatile("ld.acquire.gpu.global.u32 %0, [%1];" : "=r"(v) : "l"(p) : "memory");
    return v;
}

// ---------------- noinline phases (isolate register pressure) ----------------
__device__ __noinline__ void transpose_phase(const float* __restrict__ x,
                                             float* tile, int tid, int bx)
{
    for (int tt = 0; tt < 4; ++tt) {
        int t = bx * 4 + tt;
        const float* src = x + (size_t)t * (B_N * I_N);
        for (int idx = tid; idx < B_N * I_N; idx += NTHR)
            tile[(idx >> 7) * 129 + (idx & 127)] = src[idx];
        __syncthreads();
        float* dst = g_xT + (size_t)t * (I_N * B_N);
        for (int idx = tid; idx < I_N * B_N; idx += NTHR)
            dst[idx] = tile[(idx & 63) * 129 + (idx >> 6)];
        __syncthreads();
    }
}

__device__ __noinline__ void proj_phase(const float* __restrict__ W_out,
                                        const float* __restrict__ b_out,
                                        float* __restrict__ d_out,
                                        char* smem, int tid, int bx)
{
    float* At = (float*)(smem + 0);          // [32][64]
    float* Wt = (float*)(smem + 8192);       // [32][128]
    const int ptx = tid & 63;                // output pair column (o = 2*ptx)
    const int pty = tid >> 6;                // batch group of 4 (0..15)
    const float2 bo2 = *(const float2*)(b_out + 2 * ptx);

    for (int tt = 0; tt < 4; ++tt) {
        int tq = bx * 4 + tt;
        const float* Asrc = g_HallT + (size_t)tq * 32768;
        float2 acc[2][2];
#pragma unroll
        for (int p = 0; p < 2; ++p) {
            acc[p][0] = make_float2(0.f, 0.f);
            acc[p][1] = make_float2(0.f, 0.f);
        }
        for (int c = 0; c < 16; ++c) {
            __syncthreads();
            if (tid < 512)
                ((float4*)At)[tid] = ((const float4*)(Asrc + (size_t)c * 2048))[tid];
            ((float4*)Wt)[tid] = ((const float4*)(W_out + (size_t)c * 4096))[tid];
            __syncthreads();
#pragma unroll 4
            for (int k = 0; k < 32; ++k) {
                float4 A0 = *(const float4*)(At + k * 64 + pty * 4);
                float2 wp = *(const float2*)(Wt + k * 128 + 2 * ptx);
                float2 w0 = make_float2(wp.x, wp.x);
                float2 w1 = make_float2(wp.y, wp.y);
                float2 a0 = make_float2(A0.x, A0.y), a1 = make_float2(A0.z, A0.w);
                acc[0][0] = ffma2(a0, w0, acc[0][0]);
                acc[0][1] = ffma2(a0, w1, acc[0][1]);
                acc[1][0] = ffma2(a1, w0, acc[1][0]);
                acc[1][1] = ffma2(a1, w1, acc[1][1]);
            }
        }
        float* orow = d_out + (size_t)tq * (B_N * O_N);
#pragma unroll
        for (int p = 0; p < 2; ++p) {
            int b0 = pty * 4 + 2 * p;
            float2 r0 = make_float2(acc[p][0].x + bo2.x, acc[p][1].x + bo2.y);
            float2 r1 = make_float2(acc[p][0].y + bo2.x, acc[p][1].y + bo2.y);
            *(float2*)(orow + (size_t)b0 * O_N + 2 * ptx) = r0;
            *(float2*)(orow + (size_t)(b0 + 1) * O_N + 2 * ptx) = r1;
        }
    }
}

// ---------------- persistent fused kernel ----------------
// tid = ks*32 + j*8 + bq ; ks=0..31 k-split (4 kk each), j=0..3 hidden, bq=0..7.
struct Acc { float2 a[3][4]; };

__device__ __forceinline__ void acc_zero(Acc& A) {
#pragma unroll
    for (int g = 0; g < 3; ++g)
#pragma unroll
        for (int p = 0; p < 4; ++p) A.a[g][p] = make_float2(0.f, 0.f);
}

__device__ __forceinline__ void gemm_part(
    const float4* __restrict__ z4, const float4* __restrict__ wv,
    const float2* __restrict__ wcv, Acc& A, int kk0, int kk1)
{
#pragma unroll
    for (int kk = kk0; kk < kk1; ++kk) {
        float4 Z0 = z4[kk * 16];
        float4 Z1 = z4[kk * 16 + 8];
        float4 w4 = wv[kk * 4];
        float2 wc = wcv[kk * 4];
        float2 wi = make_float2(w4.x, w4.y);
        float2 wo = make_float2(w4.z, w4.w);
        float2 a0 = make_float2(Z0.x, Z0.y), a1 = make_float2(Z0.z, Z0.w);
        float2 a2 = make_float2(Z1.x, Z1.y), a3 = make_float2(Z1.z, Z1.w);
        A.a[0][0] = ffma2(a0, wi, A.a[0][0]);
        A.a[0][1] = ffma2(a1, wi, A.a[0][1]);
        A.a[0][2] = ffma2(a2, wi, A.a[0][2]);
        A.a[0][3] = ffma2(a3, wi, A.a[0][3]);
        A.a[1][0] = ffma2(a0, wo, A.a[1][0]);
        A.a[1][1] = ffma2(a1, wo, A.a[1][1]);
        A.a[1][2] = ffma2(a2, wo, A.a[1][2]);
        A.a[1][3] = ffma2(a3, wo, A.a[1][3]);
        A.a[2][0] = ffma2(a0, wc, A.a[2][0]);
        A.a[2][1] = ffma2(a1, wc, A.a[2][1]);
        A.a[2][2] = ffma2(a2, wc, A.a[2][2]);
        A.a[2][3] = ffma2(a3, wc, A.a[2][3]);
    }
}

__device__ __forceinline__ void commit_chunk(uint32_t dst, const float* __restrict__ src, int tid) {
#pragma unroll
    for (int r = 0; r < 2; ++r) {
        int g = tid + r * NTHR;
        cp16(dst + (uint32_t)g * 16u, src + (size_t)g * 4);
    }
    CP_COMMIT();
}

__global__ void __launch_bounds__(NTHR, 1) recurrent_kernel(
    const float* __restrict__ x,
    const float* __restrict__ W_i, const float* __restrict__ b_i,
    const float* __restrict__ W_o, const float* __restrict__ b_o,
    const float* __restrict__ W_c, const float* __restrict__ b_c,
    const float* __restrict__ W_out, const float* __restrict__ b_out,
    const float* __restrict__ dv,
    float* __restrict__ d_out)
{
    extern __shared__ char smem[];
    const int tid = threadIdx.x;
    const int ks  = tid >> 5;           // 0..31
    const int j   = (tid >> 3) & 3;
    const int bq  = tid & 7;
    const int nhb = blockIdx.x * 4;

    float4* wio = (float4*)(smem + OFF_WIO);
    float2* wcc = (float2*)(smem + OFF_WC2);
    float2* ch  = (float2*)(smem + OFF_CH);
    float*  wds = (float*) (smem + OFF_WD);
    float2* red = (float2*)(smem + OFF_RED);

    // monotonic barrier base (each CTA reads only its own flag)
    const unsigned base = g_flags[blockIdx.x * 32];

    // ---- phase 1: stage weights + wd + chist ----
    for (int idx = tid; idx < (I_N + H_N) * 4; idx += NTHR) {
        int kg = idx >> 2, jj = idx & 3;
        float wi = W_i[(size_t)kg * H_N + nhb + jj];
        float wo = W_o[(size_t)kg * H_N + nhb + jj];
        float wc = W_c[(size_t)kg * H_N + nhb + jj];
        wio[idx] = make_float4(wi, wi, wo, wo);
        wcc[idx] = make_float2(wc, wc);
    }
    for (int idx = tid; idx < KLAG * 4 * 32; idx += NTHR)
        ch[idx] = make_float2(0.f, 0.f);
    if (tid < 4) {
        float d = 0.5f / (1.0f + expf(-dv[nhb + tid]));
        float v = 1.0f;
        for (int i = 0; i < KLAG; ++i) {
            v = v * ((float)i - d) / ((float)i + 1.0f);
            wds[(KLAG - 1 - i) * 4 + tid] = v;
        }
    }
    float bi = 0.f, bo = 0.f, bc = 0.f;
    if (tid < 128) {
        int nh = nhb + (tid >> 5);
        bi = b_i[nh]; bo = b_o[nh]; bc = b_c[nh];
    }

    // ---- phase 2: transpose this CTA's 4 x-slices ----
    __syncthreads();
    transpose_phase(x, (float*)(smem + OFF_HB), tid, blockIdx.x);
    if (tid == 0) flag_store(&g_flags[blockIdx.x * 32], base + 1);
    if (tid < 128) {
        while (flag_load(&g_flags[tid * 32]) < base + 1) { }
    }
    __syncthreads();

    const uint32_t sb = smem_u32(smem);
    const uint32_t XB = sb + OFF_XBUF;
    const uint32_t HB0 = sb + OFF_HB, HB1 = HB0 + 32768u, HB2 = HB0 + 65536u;

    const int zoff = ks * 64 + bq;     // float4 index within a chunk buffer
    const float4* xz  = (const float4*)(smem + OFF_XBUF) + zoff;
    const float4* hz  = (const float4*)(smem + OFF_HB) + zoff;   // +2048/+4096 for HB1/2
    const float4* wvT = wio + ks * 16 + j;    // + c*512 per chunk
    const float2* wcT = wcc + ks * 16 + j;

    Acc A;
    acc_zero(A);

    // prologue: x(0) -> xbuf, compute x-part(0); commit h chunks 0..2 from zeros
    commit_chunk(XB, g_xT, tid);
    CP_WAIT(0);
    __syncthreads();
    gemm_part(xz, wvT, wcT, A, 0, 4);
    commit_chunk(HB0, g_zero, tid);
    commit_chunk(HB1, g_zero + 8192, tid);
    commit_chunk(HB2, g_zero + 16384, tid);

    for (int t = 0; t < T_STEPS; ++t) {
        const float* hsrc = (t == 0) ? g_zero : (g_HallT + (size_t)(t - 1) * 32768);
        const bool nl = (t < T_STEPS - 1);

        // h chunk 1
        CP_WAIT(2);
        __syncthreads();
        gemm_part(hz, wvT + 512, wcT + 512, A, 0, 4);
        __syncthreads();                         // HB0 free
        commit_chunk(HB0, hsrc + 24576, tid);    // h chunk 4
        if (nl) commit_chunk(XB, g_xT + (size_t)(t + 1) * 8192, tid);

        // h chunk 2
        if (nl) { CP_WAIT(3); } else { CP_WAIT(2); }
        __syncthreads();
        gemm_part(hz + 2048, wvT + 1024, wcT + 1024, A, 0, 4);

        // h chunk 3
        if (nl) { CP_WAIT(2); } else { CP_WAIT(1); }
        __syncthreads();
        gemm_part(hz + 4096, wvT + 1536, wcT + 1536, A, 0, 4);

        // h chunk 4
        if (nl) { CP_WAIT(1); } else { CP_WAIT(0); }
        __syncthreads();
        gemm_part(hz, wvT + 2048, wcT + 2048, A, 0, 4);

        CP_WAIT(0);          // x(t+1) landed (no-op at t=511)
        __syncthreads();     // all computes done; red (aliases HB) safe; xbuf visible

        // two-stage k-split reduction:
        // stage A: upper 16 k-splits spill
        if (tid >= 512) {
            float2* mr = red + (size_t)(tid - 512) * 13;
#pragma unroll
            for (int g = 0; g < 3; ++g)
#pragma unroll
                for (int p = 0; p < 4; ++p) mr[g * 4 + p] = A.a[g][p];
        }
        __syncthreads();
        // stage B: lower threads merge partner partials, re-spill
        if (tid < 512) {
            float2* mr = red + (size_t)tid * 13;
#pragma unroll
            for (int g = 0; g < 3; ++g)
#pragma unroll
                for (int p = 0; p < 4; ++p) {
                    float2 o = mr[g * 4 + p];
                    A.a[g][p].x += o.x; A.a[g][p].y += o.y;
                    mr[g * 4 + p] = A.a[g][p];
                }
        }
        __syncthreads();

        if (tid < 128) {  // tail: warps 0-3
            const int w = tid >> 5, l = tid & 31;
            const int bqt = (l & 15) >> 1;
            const int slot = (l & 1) + ((l >> 4) << 1);
            float2 pi = make_float2(bi, bi), po = make_float2(bo, bo), pc = make_float2(bc, bc);
#pragma unroll
            for (int k2 = 0; k2 < 16; ++k2) {
                const float2* r = red + (size_t)((k2 * 4 + w) * 8 + bqt) * 13;
                float2 r0 = r[slot], r1 = r[4 + slot], r2 = r[8 + slot];
                pi.x += r0.x; pi.y += r0.y;
                po.x += r1.x; po.y += r1.y;
                pc.x += r2.x; pc.y += r2.y;
            }
            float2 f0 = make_float2(0.f, 0.f), f1 = f0, f2 = f0, f3 = f0;
#pragma unroll
            for (int lag = 0; lag < KLAG; lag += 4) {
                float w0 = wds[(lag    ) * 4 + w];
                float w1 = wds[(lag + 1) * 4 + w];
                float w2 = wds[(lag + 2) * 4 + w];
                float w3 = wds[(lag + 3) * 4 + w];
                f0 = ffma2(ch[(size_t)(((t + lag    ) & 31) * 4 + w) * 32 + l], make_float2(w0, w0), f0);
                f1 = ffma2(ch[(size_t)(((t + lag + 1) & 31) * 4 + w) * 32 + l], make_float2(w1, w1), f1);
                f2 = ffma2(ch[(size_t)(((t + lag + 2) & 31) * 4 + w) * 32 + l], make_float2(w2, w2), f2);
                f3 = ffma2(ch[(size_t)(((t + lag + 3) & 31) * 4 + w) * 32 + l], make_float2(w3, w3), f3);
            }
            float2 frac = make_float2((f0.x + f1.x) + (f2.x + f3.x),
                                      (f0.y + f1.y) + (f2.y + f3.y));
            float2 ig = make_float2(sigf(pi.x), sigf(pi.y));
            float2 og = make_float2(sigf(po.x), sigf(po.y));
            float2 gg = make_float2(tanh_f(pc.x), tanh_f(pc.y));
            float2 c2 = make_float2(ig.x * gg.x - frac.x, ig.y * gg.y - frac.y);
            ch[(size_t)((t & 31) * 4 + w) * 32 + l] = c2;
            float2 h2 = make_float2(og.x * tanh_f(c2.x), og.y * tanh_f(c2.y));

            int nh = nhb + w;
            *(float2*)&g_HallT[(size_t)t * 32768 + (size_t)nh * 64 + 2 * l] = h2;
            if (t == T_STEPS - 1) {
                d_out[OUT_HLAST + (size_t)(2 * l) * H_N + nh]     = h2.x;
                d_out[OUT_HLAST + (size_t)(2 * l + 1) * H_N + nh] = h2.y;
            }
            asm volatile("bar.sync 1, 128;" ::: "memory");
            if (tid == 0) flag_store(&g_flags[blockIdx.x * 32], base + 2 + t);
        }

        if (nl) {
            acc_zero(A);
            gemm_part(xz, wvT, wcT, A, 0, 2);     // x-part(t+1), first half
            if (tid >= 128 && tid < 256) {        // pollers: warps 4-7
                unsigned tgt = base + 2 + t;
                while (flag_load(&g_flags[(tid - 128) * 32]) < tgt) { }
            }
            __syncthreads();
            const float* hn = g_HallT + (size_t)t * 32768;
            commit_chunk(HB0, hn, tid);
            commit_chunk(HB1, hn + 8192, tid);
            commit_chunk(HB2, hn + 16384, tid);
            gemm_part(xz, wvT, wcT, A, 2, 4);     // x-part(t+1), second half
        }
    }

    __syncthreads();
    // dump hc_last: slot l == lag l (512 % 32 == 0)
    {
        const float* chf = (const float*)ch;
        for (int idx = tid; idx < KLAG * B_N * 4; idx += NTHR) {
            int l = idx >> 8;
            int rem = idx & 255;
            int b = rem >> 2;
            int jj = rem & 3;
            float v = chf[((size_t)(l * 4 + jj) * 32 + (b >> 1)) * 2 + (b & 1)];
            d_out[OUT_HC + (size_t)l * (B_N * H_N) + (size_t)b * H_N + nhb + jj] = v;
        }
    }

    // final grid barrier: all h(t) visible everywhere (ends at base+513)
    if (tid == 0) flag_store(&g_flags[blockIdx.x * 32], base + 513);
    if (tid < 128) {
        while (flag_load(&g_flags[tid * 32]) < base + 513) { }
    }
    __syncthreads();

    // ---- phase 4: output projection for this CTA's 4 t-tiles ----
    proj_phase(W_out, b_out, d_out, smem, tid, blockIdx.x);
}

// ---------------- launch ----------------
extern "C" void kernel_launch(void* const* d_in, const int* in_sizes, int n_in,
                              void* d_out, int out_size)
{
    (void)in_sizes; (void)n_in; (void)out_size;
    const float* x     = (const float*)d_in[0];
    const float* W_i   = (const float*)d_in[1];
    const float* b_i   = (const float*)d_in[2];
    const float* W_o   = (const float*)d_in[3];
    const float* b_o   = (const float*)d_in[4];
    const float* W_c   = (const float*)d_in[5];
    const float* b_c   = (const float*)d_in[6];
    const float* W_out = (const float*)d_in[7];
    const float* b_out = (const float*)d_in[8];
    const float* dv    = (const float*)d_in[9];
    float* out = (float*)d_out;

    cudaFuncSetAttribute(recurrent_kernel,
                         cudaFuncAttributeMaxDynamicSharedMemorySize, SMEM_TOTAL);

    recurrent_kernel<<<NCTA, NTHR, SMEM_TOTAL>>>(
        x, W_i, b_i, W_o, b_o, W_c, b_c, W_out, b_out, dv, out);
}

// round 10
// speedup vs baseline: 1.0687x; 1.0687x over previous
#include <cuda_runtime.h>
#include <cstdint>

#define T_STEPS 512
#define B_N 64
#define I_N 128
#define H_N 512
#define O_N 128
#define KLAG 32
#define NCTA 128
#define NTHR 1024

// d_out layout: outputs [512,64,128] | h_last [64,512] | hc_last [32,64,512]
#define OUT_HLAST 4194304
#define OUT_HC    4227072

// smem byte offsets
#define OFF_XBUF 0u
#define OFF_HB   32768u          // 3 x 32KB ring
#define OFF_RED  32768u          // aliases HB (512 slots x 13 float2 = 53KB)
#define OFF_WIO  131072u         // [640][4] float4 (wi,wi,wo,wo)
#define OFF_WC2  172032u         // [640][4] float2 (wc,wc)
#define OFF_CH   192512u         // chist [32][4][32] float2
#define OFF_WD   225280u         // wd [32][4] float
#define OFF_MBAR 225792u         // 5 mbarriers (8B each)
#define SMEM_TOTAL 225856

// ---------------- device scratch ----------------
__device__ float g_xT[(size_t)T_STEPS * I_N * B_N];      // [t][i][b]
__device__ float g_HallT[(size_t)T_STEPS * H_N * B_N];   // [t][h][b]
__device__ float g_zero[H_N * B_N];                      // never written
__device__ unsigned g_flags[NCTA * 32];                  // 128B-strided flags (monotonic)

// ---------------- helpers ----------------
union F2U { float2 f; unsigned long long u; };

__device__ __forceinline__ float2 ffma2(float2 a, float2 b, float2 c) {
    F2U ua, ub, uc, ud;
    ua.f = a; ub.f = b; uc.f = c;
    asm("fma.rn.f32x2 %0, %1, %2, %3;" : "=l"(ud.u) : "l"(ua.u), "l"(ub.u), "l"(uc.u));
    return ud.f;
}
__device__ __forceinline__ uint32_t smem_u32(const void* p) {
    return (uint32_t)__cvta_generic_to_shared(p);
}

__device__ __forceinline__ float sigf(float x) { return 1.0f / (1.0f + __expf(-x)); }
__device__ __forceinline__ float tanh_f(float x) {
    float e = __expf(2.0f * x);
    return 1.0f - __fdividef(2.0f, e + 1.0f);
}
__device__ __forceinline__ void flag_store(unsigned* p, unsigned v) {
    asm volatile("st.release.gpu.global.u32 [%0], %1;" :: "l"(p), "r"(v) : "memory");
}
__device__ __forceinline__ unsigned flag_load(const unsigned* p) {
    unsigned v;
    asm volatile("ld.acquire.gpu.global.u32 %0, [%1];" : "=r"(v) : "l"(p) : "memory");
    return v;
}

// ---- TMA bulk + mbarrier ----
__device__ __forceinline__ void mbar_init(uint32_t mbar, unsigned count) {
    asm volatile("mbarrier.init.shared.b64 [%0], %1;" :: "r"(mbar), "r"(count) : "memory");
}
__device__ __forceinline__ void fence_async() {
    asm volatile("fence.proxy.async.shared::cta;" ::: "memory");
}
__device__ __forceinline__ void bulk_commit(uint32_t mbar, uint32_t dst, const void* src) {
    asm volatile("mbarrier.arrive.expect_tx.shared.b64 _, [%0], %1;"
                 :: "r"(mbar), "r"(32768u) : "memory");
    asm volatile("cp.async.bulk.shared::cluster.global.mbarrier::complete_tx::bytes "
                 "[%0], [%1], %2, [%3];"
                 :: "r"(dst), "l"(src), "r"(32768u), "r"(mbar) : "memory");
}
__device__ __forceinline__ void mbar_wait(uint32_t mbar, unsigned parity) {
    unsigned done = 0;
    while (!done) {
        asm volatile(
            "{\n\t.reg .pred p;\n\t"
            "mbarrier.try_wait.parity.acquire.cta.shared::cta.b64 p, [%1], %2, 0x989680;\n\t"
            "selp.b32 %0, 1, 0, p;\n\t}"
            : "=r"(done) : "r"(mbar), "r"(parity) : "memory");
    }
}

// ---------------- noinline phases (isolate register pressure) ----------------
__device__ __noinline__ void transpose_phase(const float* __restrict__ x,
                                             float* tile, int tid, int bx)
{
    for (int tt = 0; tt < 4; ++tt) {
        int t = bx * 4 + tt;
        const float* src = x + (size_t)t * (B_N * I_N);
        for (int idx = tid; idx < B_N * I_N; idx += NTHR)
            tile[(idx >> 7) * 129 + (idx & 127)] = src[idx];
        __syncthreads();
        float* dst = g_xT + (size_t)t * (I_N * B_N);
        for (int idx = tid; idx < I_N * B_N; idx += NTHR)
            dst[idx] = tile[(idx & 63) * 129 + (idx >> 6)];
        __syncthreads();
    }
}

__device__ __noinline__ void proj_phase(const float* __restrict__ W_out,
                                        const float* __restrict__ b_out,
                                        float* __restrict__ d_out,
                                        char* smem, int tid, int bx)
{
    float* At = (float*)(smem + 0);          // [32][64]
    float* Wt = (float*)(smem + 8192);       // [32][128]
    const int ptx = tid & 63;                // output pair column (o = 2*ptx)
    const int pty = tid >> 6;                // batch group of 4 (0..15)
    const float2 bo2 = *(const float2*)(b_out + 2 * ptx);

    for (int tt = 0; tt < 4; ++tt) {
        int tq = bx * 4 + tt;
        const float* Asrc = g_HallT + (size_t)tq * 32768;
        float2 acc[2][2];
#pragma unroll
        for (int p = 0; p < 2; ++p) {
            acc[p][0] = make_float2(0.f, 0.f);
            acc[p][1] = make_float2(0.f, 0.f);
        }
        for (int c = 0; c < 16; ++c) {
            __syncthreads();
            if (tid < 512)
                ((float4*)At)[tid] = ((const float4*)(Asrc + (size_t)c * 2048))[tid];
            ((float4*)Wt)[tid] = ((const float4*)(W_out + (size_t)c * 4096))[tid];
            __syncthreads();
#pragma unroll 4
            for (int k = 0; k < 32; ++k) {
                float4 A0 = *(const float4*)(At + k * 64 + pty * 4);
                float2 wp = *(const float2*)(Wt + k * 128 + 2 * ptx);
                float2 w0 = make_float2(wp.x, wp.x);
                float2 w1 = make_float2(wp.y, wp.y);
                float2 a0 = make_float2(A0.x, A0.y), a1 = make_float2(A0.z, A0.w);
                acc[0][0] = ffma2(a0, w0, acc[0][0]);
                acc[0][1] = ffma2(a0, w1, acc[0][1]);
                acc[1][0] = ffma2(a1, w0, acc[1][0]);
                acc[1][1] = ffma2(a1, w1, acc[1][1]);
            }
        }
        float* orow = d_out + (size_t)tq * (B_N * O_N);
#pragma unroll
        for (int p = 0; p < 2; ++p) {
            int b0 = pty * 4 + 2 * p;
            float2 r0 = make_float2(acc[p][0].x + bo2.x, acc[p][1].x + bo2.y);
            float2 r1 = make_float2(acc[p][0].y + bo2.x, acc[p][1].y + bo2.y);
            *(float2*)(orow + (size_t)b0 * O_N + 2 * ptx) = r0;
            *(float2*)(orow + (size_t)(b0 + 1) * O_N + 2 * ptx) = r1;
        }
    }
}

// ---------------- persistent fused kernel ----------------
// tid = ks*32 + j*8 + bq ; ks=0..31 k-split (4 kk each), j=0..3 hidden, bq=0..7.
struct Acc { float2 a[3][4]; };

__device__ __forceinline__ void acc_zero(Acc& A) {
#pragma unroll
    for (int g = 0; g < 3; ++g)
#pragma unroll
        for (int p = 0; p < 4; ++p) A.a[g][p] = make_float2(0.f, 0.f);
}

__device__ __forceinline__ void gemm_part(
    const float4* __restrict__ z4, const float4* __restrict__ wv,
    const float2* __restrict__ wcv, Acc& A, int kk0, int kk1)
{
#pragma unroll
    for (int kk = kk0; kk < kk1; ++kk) {
        float4 Z0 = z4[kk * 16];
        float4 Z1 = z4[kk * 16 + 8];
        float4 w4 = wv[kk * 4];
        float2 wc = wcv[kk * 4];
        float2 wi = make_float2(w4.x, w4.y);
        float2 wo = make_float2(w4.z, w4.w);
        float2 a0 = make_float2(Z0.x, Z0.y), a1 = make_float2(Z0.z, Z0.w);
        float2 a2 = make_float2(Z1.x, Z1.y), a3 = make_float2(Z1.z, Z1.w);
        A.a[0][0] = ffma2(a0, wi, A.a[0][0]);
        A.a[0][1] = ffma2(a1, wi, A.a[0][1]);
        A.a[0][2] = ffma2(a2, wi, A.a[0][2]);
        A.a[0][3] = ffma2(a3, wi, A.a[0][3]);
        A.a[1][0] = ffma2(a0, wo, A.a[1][0]);
        A.a[1][1] = ffma2(a1, wo, A.a[1][1]);
        A.a[1][2] = ffma2(a2, wo, A.a[1][2]);
        A.a[1][3] = ffma2(a3, wo, A.a[1][3]);
        A.a[2][0] = ffma2(a0, wc, A.a[2][0]);
        A.a[2][1] = ffma2(a1, wc, A.a[2][1]);
        A.a[2][2] = ffma2(a2, wc, A.a[2][2]);
        A.a[2][3] = ffma2(a3, wc, A.a[2][3]);
    }
}

__global__ void __launch_bounds__(NTHR, 1) recurrent_kernel(
    const float* __restrict__ x,
    const float* __restrict__ W_i, const float* __restrict__ b_i,
    const float* __restrict__ W_o, const float* __restrict__ b_o,
    const float* __restrict__ W_c, const float* __restrict__ b_c,
    const float* __restrict__ W_out, const float* __restrict__ b_out,
    const float* __restrict__ dv,
    float* __restrict__ d_out)
{
    extern __shared__ char smem[];
    const int tid = threadIdx.x;
    const int ks  = tid >> 5;           // 0..31
    const int j   = (tid >> 3) & 3;
    const int bq  = tid & 7;
    const int nhb = blockIdx.x * 4;

    float4* wio = (float4*)(smem + OFF_WIO);
    float2* wcc = (float2*)(smem + OFF_WC2);
    float2* ch  = (float2*)(smem + OFF_CH);
    float*  wds = (float*) (smem + OFF_WD);
    float2* red = (float2*)(smem + OFF_RED);

    // monotonic barrier base (each CTA reads only its own flag)
    const unsigned base = g_flags[blockIdx.x * 32];

    const uint32_t sb = smem_u32(smem);
    const uint32_t XB = sb + OFF_XBUF;
    const uint32_t HB0 = sb + OFF_HB, HB1 = HB0 + 32768u, HB2 = HB0 + 65536u;
    const uint32_t MB0 = sb + OFF_MBAR;          // x role
    const uint32_t MB1 = MB0 + 8, MB2 = MB0 + 16, MB3 = MB0 + 24, MB4 = MB0 + 32;

    // ---- phase 1: stage weights + wd + chist + mbar init ----
    if (tid == 0) {
        mbar_init(MB0, 1); mbar_init(MB1, 1); mbar_init(MB2, 1);
        mbar_init(MB3, 1); mbar_init(MB4, 1);
        fence_async();
    }
    for (int idx = tid; idx < (I_N + H_N) * 4; idx += NTHR) {
        int kg = idx >> 2, jj = idx & 3;
        float wi = W_i[(size_t)kg * H_N + nhb + jj];
        float wo = W_o[(size_t)kg * H_N + nhb + jj];
        float wc = W_c[(size_t)kg * H_N + nhb + jj];
        wio[idx] = make_float4(wi, wi, wo, wo);
        wcc[idx] = make_float2(wc, wc);
    }
    for (int idx = tid; idx < KLAG * 4 * 32; idx += NTHR)
        ch[idx] = make_float2(0.f, 0.f);
    if (tid < 4) {
        float d = 0.5f / (1.0f + expf(-dv[nhb + tid]));
        float v = 1.0f;
        for (int i = 0; i < KLAG; ++i) {
            v = v * ((float)i - d) / ((float)i + 1.0f);
            wds[(KLAG - 1 - i) * 4 + tid] = v;
        }
    }
    float bi = 0.f, bo = 0.f, bc = 0.f;
    if (tid < 128) {
        int nh = nhb + (tid >> 5);
        bi = b_i[nh]; bo = b_o[nh]; bc = b_c[nh];
    }

    // ---- phase 2: transpose this CTA's 4 x-slices ----
    __syncthreads();
    transpose_phase(x, (float*)(smem + OFF_HB), tid, blockIdx.x);
    if (tid == 0) flag_store(&g_flags[blockIdx.x * 32], base + 1);
    if (tid < 128) {
        while (flag_load(&g_flags[tid * 32]) < base + 1) { }
    }
    __syncthreads();

    const int zoff = ks * 64 + bq;     // float4 index within a chunk buffer
    const float4* xz  = (const float4*)(smem + OFF_XBUF) + zoff;
    const float4* hz  = (const float4*)(smem + OFF_HB) + zoff;   // +2048/+4096 for HB1/2
    const float4* wvT = wio + ks * 16 + j;    // + c*512 per chunk
    const float2* wcT = wcc + ks * 16 + j;

    Acc A;
    acc_zero(A);

    // prologue: x(0) -> xbuf via TMA, compute x-part(0); commit h chunks 1..3 (zeros)
    if (tid == 0) {
        fence_async();                     // transpose tile writes -> async proxy
        bulk_commit(MB0, XB, g_xT);
    }
    mbar_wait(MB0, 0);
    gemm_part(xz, wvT, wcT, A, 0, 4);
    if (tid == 0) {
        bulk_commit(MB1, HB0, g_zero);
        bulk_commit(MB2, HB1, g_zero + 8192);
        bulk_commit(MB3, HB2, g_zero + 16384);
    }

    for (int t = 0; t < T_STEPS; ++t) {
        const float* hsrc = (t == 0) ? g_zero : (g_HallT + (size_t)(t - 1) * 32768);
        const bool nl = (t < T_STEPS - 1);
        const unsigned par = (unsigned)(t & 1);

        // h chunk 1
        mbar_wait(MB1, par);
        gemm_part(hz, wvT + 512, wcT + 512, A, 0, 4);
        __syncthreads();                         // all done reading HB0 + XB
        if (tid == 0) {
            fence_async();                       // red spill writes (HB alias) -> async
            bulk_commit(MB4, HB0, hsrc + 24576); // h chunk 4
            if (nl) bulk_commit(MB0, XB, g_xT + (size_t)(t + 1) * 8192);
        }

        // h chunk 2
        mbar_wait(MB2, par);
        gemm_part(hz + 2048, wvT + 1024, wcT + 1024, A, 0, 4);

        // h chunk 3
        mbar_wait(MB3, par);
        gemm_part(hz + 4096, wvT + 1536, wcT + 1536, A, 0, 4);

        // h chunk 4
        mbar_wait(MB4, par);
        gemm_part(hz, wvT + 2048, wcT + 2048, A, 0, 4);

        __syncthreads();     // all computes done; red (aliases HB) safe

        // two-stage k-split reduction:
        if (tid >= 512) {
            float2* mr = red + (size_t)(tid - 512) * 13;
#pragma unroll
            for (int g = 0; g < 3; ++g)
#pragma unroll
                for (int p = 0; p < 4; ++p) mr[g * 4 + p] = A.a[g][p];
        }
        __syncthreads();
        if (tid < 512) {
            float2* mr = red + (size_t)tid * 13;
#pragma unroll
            for (int g = 0; g < 3; ++g)
#pragma unroll
                for (int p = 0; p < 4; ++p) {
                    float2 o = mr[g * 4 + p];
                    A.a[g][p].x += o.x; A.a[g][p].y += o.y;
                    mr[g * 4 + p] = A.a[g][p];
                }
        }
        __syncthreads();

        if (tid < 128) {  // tail: warps 0-3
            const int w = tid >> 5, l = tid & 31;
            const int bqt = (l & 15) >> 1;
            const int slot = (l & 1) + ((l >> 4) << 1);
            float2 pi = make_float2(bi, bi), po = make_float2(bo, bo), pc = make_float2(bc, bc);
#pragma unroll
            for (int k2 = 0; k2 < 16; ++k2) {
                const float2* r = red + (size_t)((k2 * 4 + w) * 8 + bqt) * 13;
                float2 r0 = r[slot], r1 = r[4 + slot], r2 = r[8 + slot];
                pi.x += r0.x; pi.y += r0.y;
                po.x += r1.x; po.y += r1.y;
                pc.x += r2.x; pc.y += r2.y;
            }
            float2 f0 = make_float2(0.f, 0.f), f1 = f0, f2 = f0, f3 = f0;
#pragma unroll
            for (int lag = 0; lag < KLAG; lag += 4) {
                float w0 = wds[(lag    ) * 4 + w];
                float w1 = wds[(lag + 1) * 4 + w];
                float w2 = wds[(lag + 2) * 4 + w];
                float w3 = wds[(lag + 3) * 4 + w];
                f0 = ffma2(ch[(size_t)(((t + lag    ) & 31) * 4 + w) * 32 + l], make_float2(w0, w0), f0);
                f1 = ffma2(ch[(size_t)(((t + lag + 1) & 31) * 4 + w) * 32 + l], make_float2(w1, w1), f1);
                f2 = ffma2(ch[(size_t)(((t + lag + 2) & 31) * 4 + w) * 32 + l], make_float2(w2, w2), f2);
                f3 = ffma2(ch[(size_t)(((t + lag + 3) & 31) * 4 + w) * 32 + l], make_float2(w3, w3), f3);
            }
            float2 frac = make_float2((f0.x + f1.x) + (f2.x + f3.x),
                                      (f0.y + f1.y) + (f2.y + f3.y));
            float2 ig = make_float2(sigf(pi.x), sigf(pi.y));
            float2 og = make_float2(sigf(po.x), sigf(po.y));
            float2 gg = make_float2(tanh_f(pc.x), tanh_f(pc.y));
            float2 c2 = make_float2(ig.x * gg.x - frac.x, ig.y * gg.y - frac.y);
            ch[(size_t)((t & 31) * 4 + w) * 32 + l] = c2;
            float2 h2 = make_float2(og.x * tanh_f(c2.x), og.y * tanh_f(c2.y));

            int nh = nhb + w;
            *(float2*)&g_HallT[(size_t)t * 32768 + (size_t)nh * 64 + 2 * l] = h2;
            if (t == T_STEPS - 1) {
                d_out[OUT_HLAST + (size_t)(2 * l) * H_N + nh]     = h2.x;
                d_out[OUT_HLAST + (size_t)(2 * l + 1) * H_N + nh] = h2.y;
            }
            asm volatile("bar.sync 1, 128;" ::: "memory");
            if (tid == 0) flag_store(&g_flags[blockIdx.x * 32], base + 2 + t);
        }

        if (nl) {
            acc_zero(A);
            mbar_wait(MB0, (unsigned)((t + 1) & 1));   // x(t+1) landed
            gemm_part(xz, wvT, wcT, A, 0, 2);          // x-part(t+1), first half
            if (tid >= 128 && tid < 256) {             // pollers: warps 4-7
                unsigned tgt = base + 2 + t;
                while (flag_load(&g_flags[(tid - 128) * 32]) < tgt) { }
            }
            __syncthreads();
            if (tid == 0) {
                fence_async();                         // spill writes (red=HB alias)
                const float* hn = g_HallT + (size_t)t * 32768;
                bulk_commit(MB1, HB0, hn);
                bulk_commit(MB2, HB1, hn + 8192);
                bulk_commit(MB3, HB2, hn + 16384);
            }
            gemm_part(xz, wvT, wcT, A, 2, 4);          // x-part(t+1), second half
        }
    }

    __syncthreads();
    // dump hc_last: slot l == lag l (512 % 32 == 0)
    {
        const float* chf = (const float*)ch;
        for (int idx = tid; idx < KLAG * B_N * 4; idx += NTHR) {
            int l = idx >> 8;
            int rem = idx & 255;
            int b = rem >> 2;
            int jj = rem & 3;
            float v = chf[((size_t)(l * 4 + jj) * 32 + (b >> 1)) * 2 + (b & 1)];
            d_out[OUT_HC + (size_t)l * (B_N * H_N) + (size_t)b * H_N + nhb + jj] = v;
        }
    }

    // final grid barrier: all h(t) visible everywhere (ends at base+513)
    if (tid == 0) flag_store(&g_flags[blockIdx.x * 32], base + 513);
    if (tid < 128) {
        while (flag_load(&g_flags[tid * 32]) < base + 513) { }
    }
    __syncthreads();

    // ---- phase 4: output projection for this CTA's 4 t-tiles ----
    proj_phase(W_out, b_out, d_out, smem, tid, blockIdx.x);
}

// ---------------- launch ----------------
extern "C" void kernel_launch(void* const* d_in, const int* in_sizes, int n_in,
                              void* d_out, int out_size)
{
    (void)in_sizes; (void)n_in; (void)out_size;
    const float* x     = (const float*)d_in[0];
    const float* W_i   = (const float*)d_in[1];
    const float* b_i   = (const float*)d_in[2];
    const float* W_o   = (const float*)d_in[3];
    const float* b_o   = (const float*)d_in[4];
    const float* W_c   = (const float*)d_in[5];
    const float* b_c   = (const float*)d_in[6];
    const float* W_out = (const float*)d_in[7];
    const float* b_out = (const float*)d_in[8];
    const float* dv    = (const float*)d_in[9];
    float* out = (float*)d_out;

    cudaFuncSetAttribute(recurrent_kernel,
                         cudaFuncAttributeMaxDynamicSharedMemorySize, SMEM_TOTAL);

    recurrent_kernel<<<NCTA, NTHR, SMEM_TOTAL>>>(
        x, W_i, b_i, W_o, b_o, W_c, b_c, W_out, b_out, dv, out);
}